// round 2
// baseline (speedup 1.0000x reference)
#include <cuda_runtime.h>
#include <math.h>

#define HW     128
#define BATCH  2
#define CH     128
#define NPIX   (HW*HW)            // 16384
#define ITERS  10

// ---------------- scratch (static device allocations; no cudaMalloc) ----------------
__device__ float g_lf0 [BATCH*CH*NPIX];
__device__ float g_lf1 [BATCH*CH*NPIX];
__device__ float g_tmp [BATCH*CH*NPIX];      // conv intermediate / h1
__device__ float g_x   [BATCH*NPIX*CH];      // channel-last attention input
__device__ float g_q   [BATCH*NPIX*CH];      // channel-last
__device__ float g_k   [BATCH*NPIX*CH];      // channel-last
__device__ float g_flow[BATCH*2*NPIX];
__device__ float g_fi  [BATCH*2*NPIX];
__device__ float g_t16a[BATCH*16*NPIX];
__device__ float g_t16b[BATCH*16*NPIX];
__device__ float g_d   [BATCH*2*NPIX];
__device__ float g_hcat[BATCH*258*NPIX];
__device__ float g_h2  [BATCH*64*NPIX];

// ---------------- helpers ----------------
__device__ __forceinline__ float gelu_f(float v) {
    return 0.5f * v * (1.0f + erff(v * 0.70710678118654752f));
}
__device__ __forceinline__ float sigmoid_f(float v) {
    return 1.0f / (1.0f + expf(-v));
}

#define ACT_NONE 0
#define ACT_GELU 1
#define ACT_SIGM 2

// ---------------- generic NCHW 3x3 conv, pad=1 ----------------
// block: 256 threads (16x16), each thread computes a 2x2 pixel microtile for 8
// output channels. cin staged 4 at a time through smem.
__global__ __launch_bounds__(256) void conv3x3_kernel(
    const float* __restrict__ in, const float* __restrict__ wgt,
    const float* __restrict__ bias, float* __restrict__ out,
    int Cin, int Cout, int act)
{
    __shared__ float s_in[4][34][34];
    __shared__ float s_w[4][8][9];

    const int tid = threadIdx.x;
    const int tx = tid & 15, ty = tid >> 4;
    const int x0 = blockIdx.x * 32, y0 = blockIdx.y * 32;
    const int nco = (Cout + 7) >> 3;
    const int bb  = blockIdx.z / nco;
    const int co0 = (blockIdx.z % nco) * 8;

    float acc[2][2][8];
    #pragma unroll
    for (int i = 0; i < 2; i++)
        #pragma unroll
        for (int j = 0; j < 2; j++)
            #pragma unroll
            for (int c = 0; c < 8; c++) acc[i][j][c] = 0.f;

    for (int c0 = 0; c0 < Cin; c0 += 4) {
        // load 4 input tiles (34x34, with -1 halo, zero pad)
        for (int idx = tid; idx < 4 * 1156; idx += 256) {
            int ci = idx / 1156;
            int r  = (idx % 1156) / 34;
            int cc = idx % 34;
            int gy = y0 - 1 + r, gx = x0 - 1 + cc;
            int cin = c0 + ci;
            float v = 0.f;
            if (cin < Cin && (unsigned)gy < (unsigned)HW && (unsigned)gx < (unsigned)HW)
                v = in[((size_t)(bb * Cin + cin) * HW + gy) * HW + gx];
            s_in[ci][r][cc] = v;
        }
        // load 4x8x9 weights (288 elements, 256 threads -> grid-stride!)
        for (int idx = tid; idx < 288; idx += 256) {
            int ci = idx / 72;
            int co = (idx % 72) / 9;
            int k  = idx % 9;
            int cin = c0 + ci, cog = co0 + co;
            float v = 0.f;
            if (cin < Cin && cog < Cout)
                v = wgt[((size_t)cog * Cin + cin) * 9 + k];
            s_w[ci][co][k] = v;
        }
        __syncthreads();

        for (int ci = 0; ci < 4; ci++) {
            float v[4][4];
            #pragma unroll
            for (int i = 0; i < 4; i++)
                #pragma unroll
                for (int j = 0; j < 4; j++)
                    v[i][j] = s_in[ci][ty * 2 + i][tx * 2 + j];
            #pragma unroll
            for (int co = 0; co < 8; co++) {
                float w0 = s_w[ci][co][0], w1 = s_w[ci][co][1], w2 = s_w[ci][co][2];
                float w3 = s_w[ci][co][3], w4 = s_w[ci][co][4], w5 = s_w[ci][co][5];
                float w6 = s_w[ci][co][6], w7 = s_w[ci][co][7], w8 = s_w[ci][co][8];
                #pragma unroll
                for (int i2 = 0; i2 < 2; i2++)
                    #pragma unroll
                    for (int j2 = 0; j2 < 2; j2++) {
                        float a = acc[i2][j2][co];
                        a += v[i2+0][j2+0] * w0;
                        a += v[i2+0][j2+1] * w1;
                        a += v[i2+0][j2+2] * w2;
                        a += v[i2+1][j2+0] * w3;
                        a += v[i2+1][j2+1] * w4;
                        a += v[i2+1][j2+2] * w5;
                        a += v[i2+2][j2+0] * w6;
                        a += v[i2+2][j2+1] * w7;
                        a += v[i2+2][j2+2] * w8;
                        acc[i2][j2][co] = a;
                    }
            }
        }
        __syncthreads();
    }

    #pragma unroll
    for (int co = 0; co < 8; co++) {
        int cog = co0 + co;
        if (cog >= Cout) break;
        float bv = bias[cog];
        #pragma unroll
        for (int i2 = 0; i2 < 2; i2++)
            #pragma unroll
            for (int j2 = 0; j2 < 2; j2++) {
                int oy = y0 + ty * 2 + i2, ox = x0 + tx * 2 + j2;
                float v = acc[i2][j2][co] + bv;
                if (act == ACT_GELU) v = gelu_f(v);
                else if (act == ACT_SIGM) v = sigmoid_f(v);
                out[((size_t)(bb * Cout + cog) * HW + oy) * HW + ox] = v;
            }
    }
}

// ---------------- warp + diff + L2-normalize; emits x = 1 - diffn channel-last ----------------
// grid (256, B) : blockIdx.x -> (row y, half-row). block 128 threads.
__global__ __launch_bounds__(128) void warp_diff_kernel(
    const float* __restrict__ lf0, const float* __restrict__ lf1,
    const float* __restrict__ flow, float* __restrict__ xout)
{
    __shared__ float s_diff[64][129];
    __shared__ float s_ssq[128];
    __shared__ float s_rinv[64];

    const int tid = threadIdx.x;
    const int b = blockIdx.y;
    const int y = blockIdx.x >> 1;
    const int xbase = (blockIdx.x & 1) * 64;
    const int px = tid & 63;
    const int half = tid >> 6;
    const int x = xbase + px;

    float fx = flow[(b * 2 + 0) * NPIX + y * HW + x];
    float fy = flow[(b * 2 + 1) * NPIX + y * HW + x];
    float xs = fminf(fmaxf((float)x + fx, 0.f), 127.f);
    float ys = fminf(fmaxf((float)y + fy, 0.f), 127.f);
    float x0f = floorf(xs), y0f = floorf(ys);
    int ix0 = (int)x0f, iy0 = (int)y0f;
    int ix1 = min(ix0 + 1, 127), iy1 = min(iy0 + 1, 127);
    float wx = xs - x0f, wy = ys - y0f;
    float w00 = (1.f - wx) * (1.f - wy), w01 = wx * (1.f - wy);
    float w10 = (1.f - wx) * wy,         w11 = wx * wy;
    int o00 = iy0 * HW + ix0, o01 = iy0 * HW + ix1;
    int o10 = iy1 * HW + ix0, o11 = iy1 * HW + ix1;

    const float* lf1b = lf1 + (size_t)b * CH * NPIX;
    const float* lf0b = lf0 + (size_t)b * CH * NPIX;
    const int here = y * HW + x;

    float ssq = 0.f;
    for (int c = half * 64; c < half * 64 + 64; ++c) {
        const float* p = lf1b + (size_t)c * NPIX;
        float wv = w00 * p[o00] + w01 * p[o01] + w10 * p[o10] + w11 * p[o11];
        float d = lf0b[(size_t)c * NPIX + here] - wv;
        s_diff[px][c] = d;
        ssq += d * d;
    }
    s_ssq[tid] = ssq;
    __syncthreads();
    if (tid < 64) {
        float s = s_ssq[tid] + s_ssq[tid + 64];
        s_rinv[tid] = 1.f / fmaxf(sqrtf(s), 1e-12f);
    }
    __syncthreads();

    float* xb = xout + ((size_t)b * NPIX + y * HW + xbase) * CH;
    for (int p2 = 0; p2 < 64; ++p2)
        xb[(size_t)p2 * CH + tid] = 1.f - s_diff[p2][tid] * s_rinv[p2];
}

// ---------------- fused q/k 1x1 projection: [32768,128] x [128,128]^T ----------------
// grid (256, 2): y=0 -> q, y=1 -> k. block 256 threads, 128x128 tile, 8x8 microtile.
__global__ __launch_bounds__(256) void gemm_qk_kernel(
    const float* __restrict__ X,
    const float* __restrict__ qw, const float* __restrict__ qb,
    const float* __restrict__ kw, const float* __restrict__ kb,
    float* __restrict__ Q, float* __restrict__ Kout)
{
    __shared__ float As[8][132];
    __shared__ float Bs[8][132];

    const int tid = threadIdx.x;
    const int tx = tid & 15, ty = tid >> 4;
    const int m0 = blockIdx.x * 128;
    const bool isK = (blockIdx.y != 0);
    const float* W    = isK ? kw : qw;
    const float* bias = isK ? kb : qb;
    float* out        = isK ? Kout : Q;

    float acc[8][8];
    #pragma unroll
    for (int i = 0; i < 8; i++)
        #pragma unroll
        for (int j = 0; j < 8; j++) acc[i][j] = 0.f;

    const int row  = tid >> 1;   // 0..127
    const int part = tid & 1;

    for (int kk = 0; kk < 128; kk += 8) {
        float4 a = *(const float4*)&X[(size_t)(m0 + row) * 128 + kk + part * 4];
        float4 b = *(const float4*)&W[(size_t)row * 128 + kk + part * 4];
        As[part*4+0][row] = a.x; As[part*4+1][row] = a.y;
        As[part*4+2][row] = a.z; As[part*4+3][row] = a.w;
        Bs[part*4+0][row] = b.x; Bs[part*4+1][row] = b.y;
        Bs[part*4+2][row] = b.z; Bs[part*4+3][row] = b.w;
        __syncthreads();
        #pragma unroll
        for (int k = 0; k < 8; k++) {
            float af[8], bf[8];
            *(float4*)&af[0] = *(const float4*)&As[k][ty * 8];
            *(float4*)&af[4] = *(const float4*)&As[k][ty * 8 + 4];
            *(float4*)&bf[0] = *(const float4*)&Bs[k][tx * 8];
            *(float4*)&bf[4] = *(const float4*)&Bs[k][tx * 8 + 4];
            #pragma unroll
            for (int i = 0; i < 8; i++)
                #pragma unroll
                for (int j = 0; j < 8; j++)
                    acc[i][j] += af[i] * bf[j];
        }
        __syncthreads();
    }

    #pragma unroll
    for (int i = 0; i < 8; i++) {
        int m = m0 + ty * 8 + i;
        #pragma unroll
        for (int j = 0; j < 8; j++)
            out[(size_t)m * 128 + tx * 8 + j] = acc[i][j] + bias[tx * 8 + j];
    }
}

// ---------------- 25-tap local attention: scores->softmax->flow blend ----------------
// warp per pixel; lanes over channels; exact zero-pad semantics.
__global__ __launch_bounds__(256) void attn_kernel(
    const float* __restrict__ Q, const float* __restrict__ K,
    const float* __restrict__ flow, float* __restrict__ fi)
{
    const int lane = threadIdx.x & 31;
    const int warp = threadIdx.x >> 5;
    const int p = blockIdx.x * 8 + warp;     // 0..32767
    const int b = p >> 14;
    const int yx = p & 16383;
    const int y = yx >> 7, x = yx & 127;

    const float* qv = Q + (size_t)p * 128;
    const float q0 = qv[lane], q1 = qv[lane + 32], q2 = qv[lane + 64], q3 = qv[lane + 96];

    float s[25];
    #pragma unroll
    for (int t = 0; t < 25; t++) {
        const int dy = t / 5 - 2, dx = t % 5 - 2;
        const int ny = y + dy, nx = x + dx;
        float partial = 0.f;
        if ((unsigned)ny < (unsigned)HW && (unsigned)nx < (unsigned)HW) {
            const float* kv = K + ((size_t)(b << 14) + ny * HW + nx) * 128;
            partial = q0 * kv[lane] + q1 * kv[lane + 32] + q2 * kv[lane + 64] + q3 * kv[lane + 96];
        }
        #pragma unroll
        for (int off = 16; off; off >>= 1)
            partial += __shfl_xor_sync(0xffffffffu, partial, off);
        s[t] = partial * 0.08838834764831845f;   // 1/sqrt(128)
    }

    float mx = s[0];
    #pragma unroll
    for (int t = 1; t < 25; t++) mx = fmaxf(mx, s[t]);
    float sum = 0.f;
    #pragma unroll
    for (int t = 0; t < 25; t++) sum += expf(s[t] - mx);

    float c0 = 0.f, c1 = 0.f;
    if (lane < 25) {
        const int dy = lane / 5 - 2, dx = lane % 5 - 2;
        const int ny = y + dy, nx = x + dx;
        if ((unsigned)ny < (unsigned)HW && (unsigned)nx < (unsigned)HW) {
            const float w = expf(s[lane] - mx) / sum;
            c0 = w * flow[(size_t)(b * 2 + 0) * NPIX + ny * HW + nx];
            c1 = w * flow[(size_t)(b * 2 + 1) * NPIX + ny * HW + nx];
        }
    }
    #pragma unroll
    for (int off = 16; off; off >>= 1) {
        c0 += __shfl_xor_sync(0xffffffffu, c0, off);
        c1 += __shfl_xor_sync(0xffffffffu, c1, off);
    }
    if (lane == 0) {
        fi[(size_t)(b * 2 + 0) * NPIX + y * HW + x] = c0;
        fi[(size_t)(b * 2 + 1) * NPIX + y * HW + x] = c1;
    }
}

// ---------------- small utility kernels ----------------
__global__ void add_flow_kernel(float* __restrict__ flow, const float* __restrict__ d) {
    int i = blockIdx.x * 256 + threadIdx.x;
    if (i < BATCH * 2 * NPIX) flow[i] += d[i];
}

__global__ void copy_kernel(float* __restrict__ dst, const float* __restrict__ src, int n) {
    int i = blockIdx.x * 256 + threadIdx.x;
    if (i < n) dst[i] = src[i];
}

// pack hcat = [feat0 | warp(feat1, flow) | flow], NCHW channels 0..257
__global__ __launch_bounds__(128) void pack_kernel(
    const float* __restrict__ feat0, const float* __restrict__ feat1,
    const float* __restrict__ flow, float* __restrict__ hcat)
{
    const int x = threadIdx.x;
    const int y = blockIdx.x;
    const int b = blockIdx.y;
    const int here = y * HW + x;

    float fx = flow[(b * 2 + 0) * NPIX + here];
    float fy = flow[(b * 2 + 1) * NPIX + here];
    float xs = fminf(fmaxf((float)x + fx, 0.f), 127.f);
    float ys = fminf(fmaxf((float)y + fy, 0.f), 127.f);
    float x0f = floorf(xs), y0f = floorf(ys);
    int ix0 = (int)x0f, iy0 = (int)y0f;
    int ix1 = min(ix0 + 1, 127), iy1 = min(iy0 + 1, 127);
    float wx = xs - x0f, wy = ys - y0f;
    float w00 = (1.f - wx) * (1.f - wy), w01 = wx * (1.f - wy);
    float w10 = (1.f - wx) * wy,         w11 = wx * wy;
    int o00 = iy0 * HW + ix0, o01 = iy0 * HW + ix1;
    int o10 = iy1 * HW + ix0, o11 = iy1 * HW + ix1;

    float* hb = hcat + (size_t)b * 258 * NPIX;
    const float* f0 = feat0 + (size_t)b * CH * NPIX;
    const float* f1 = feat1 + (size_t)b * CH * NPIX;

    for (int c = 0; c < CH; c++) {
        hb[(size_t)c * NPIX + here] = f0[(size_t)c * NPIX + here];
        const float* p = f1 + (size_t)c * NPIX;
        hb[(size_t)(CH + c) * NPIX + here] =
            w00 * p[o00] + w01 * p[o01] + w10 * p[o10] + w11 * p[o11];
    }
    hb[(size_t)256 * NPIX + here] = fx;
    hb[(size_t)257 * NPIX + here] = fy;
}

// ---------------- host orchestration ----------------
static float* sym_addr(const void* symbol) {
    void* p = nullptr;
    cudaGetSymbolAddress(&p, symbol);
    return (float*)p;
}

extern "C" void kernel_launch(void* const* d_in, const int* in_sizes, int n_in,
                              void* d_out, int out_size)
{
    (void)in_sizes; (void)n_in; (void)out_size;
    const float* feat0     = (const float*)d_in[0];
    const float* feat1     = (const float*)d_in[1];
    const float* flow_init = (const float*)d_in[2];
    const float* lc_w1 = (const float*)d_in[3];
    const float* lc_b1 = (const float*)d_in[4];
    const float* lc_w2 = (const float*)d_in[5];
    const float* lc_b2 = (const float*)d_in[6];
    const float* qw    = (const float*)d_in[7];
    const float* qb    = (const float*)d_in[8];
    const float* kw    = (const float*)d_in[9];
    const float* kb    = (const float*)d_in[10];
    const float* fr_w1 = (const float*)d_in[11];
    const float* fr_b1 = (const float*)d_in[12];
    const float* fr_w2 = (const float*)d_in[13];
    const float* fr_b2 = (const float*)d_in[14];
    const float* fr_w3 = (const float*)d_in[15];
    const float* fr_b3 = (const float*)d_in[16];
    const float* cf_w1 = (const float*)d_in[17];
    const float* cf_b1 = (const float*)d_in[18];
    const float* cf_w2 = (const float*)d_in[19];
    const float* cf_b2 = (const float*)d_in[20];
    const float* cf_w3 = (const float*)d_in[21];
    const float* cf_b3 = (const float*)d_in[22];

    float* lf0  = sym_addr(g_lf0);
    float* lf1  = sym_addr(g_lf1);
    float* tmp  = sym_addr(g_tmp);
    float* xbuf = sym_addr(g_x);
    float* qbuf = sym_addr(g_q);
    float* kbuf = sym_addr(g_k);
    float* flow = sym_addr(g_flow);
    float* fi   = sym_addr(g_fi);
    float* t16a = sym_addr(g_t16a);
    float* t16b = sym_addr(g_t16b);
    float* dbuf = sym_addr(g_d);
    float* hcat = sym_addr(g_hcat);
    float* h2   = sym_addr(g_h2);
    float* out_flow = (float*)d_out;                 // [B,2,H,W] = 65536 floats
    float* out_conf = (float*)d_out + BATCH * 2 * NPIX;  // [B,1,H,W]

    const dim3 cblk(256);
    // local_conv on both features (hoisted out of the loop)
    conv3x3_kernel<<<dim3(4,4,BATCH*16), cblk>>>(feat0, lc_w1, lc_b1, tmp, 128, 128, ACT_GELU);
    conv3x3_kernel<<<dim3(4,4,BATCH*16), cblk>>>(tmp,   lc_w2, lc_b2, lf0, 128, 128, ACT_NONE);
    conv3x3_kernel<<<dim3(4,4,BATCH*16), cblk>>>(feat1, lc_w1, lc_b1, tmp, 128, 128, ACT_GELU);
    conv3x3_kernel<<<dim3(4,4,BATCH*16), cblk>>>(tmp,   lc_w2, lc_b2, lf1, 128, 128, ACT_NONE);

    copy_kernel<<<(BATCH*2*NPIX + 255)/256, 256>>>(flow, flow_init, BATCH*2*NPIX);

    for (int it = 0; it < ITERS; ++it) {
        warp_diff_kernel<<<dim3(2*HW, BATCH), 128>>>(lf0, lf1, flow, xbuf);
        gemm_qk_kernel<<<dim3(BATCH*NPIX/128, 2), 256>>>(xbuf, qw, qb, kw, kb, qbuf, kbuf);
        attn_kernel<<<BATCH*NPIX/8, 256>>>(qbuf, kbuf, flow, fi);
        conv3x3_kernel<<<dim3(4,4,BATCH*2), cblk>>>(fi,   fr_w1, fr_b1, t16a, 2, 16, ACT_GELU);
        conv3x3_kernel<<<dim3(4,4,BATCH*2), cblk>>>(t16a, fr_w2, fr_b2, t16b, 16, 16, ACT_GELU);
        conv3x3_kernel<<<dim3(4,4,BATCH*1), cblk>>>(t16b, fr_w3, fr_b3, dbuf, 16, 2, ACT_NONE);
        add_flow_kernel<<<(BATCH*2*NPIX + 255)/256, 256>>>(flow, dbuf);
    }

    // confidence head
    pack_kernel<<<dim3(HW, BATCH), 128>>>(feat0, feat1, flow, hcat);
    conv3x3_kernel<<<dim3(4,4,BATCH*16), cblk>>>(hcat, cf_w1, cf_b1, tmp, 258, 128, ACT_GELU);
    conv3x3_kernel<<<dim3(4,4,BATCH*8),  cblk>>>(tmp,  cf_w2, cf_b2, h2,  128, 64,  ACT_GELU);
    conv3x3_kernel<<<dim3(4,4,BATCH*1),  cblk>>>(h2,   cf_w3, cf_b3, out_conf, 64, 1, ACT_SIGM);

    copy_kernel<<<(BATCH*2*NPIX + 255)/256, 256>>>(out_flow, flow, BATCH*2*NPIX);
}

// round 3
// speedup vs baseline: 1.1558x; 1.1558x over previous
#include <cuda_runtime.h>
#include <math.h>

#define HW     128
#define BATCH  2
#define CH     128
#define NPIX   (HW*HW)            // 16384
#define ITERS  10

// ---------------- scratch (static device allocations; no cudaMalloc) ----------------
__device__ float g_lf0 [BATCH*CH*NPIX];
__device__ float g_lf1 [BATCH*CH*NPIX];
__device__ float g_tmp [BATCH*CH*NPIX];      // conv intermediate / h1
__device__ float g_x   [BATCH*NPIX*CH];      // channel-last attention input
__device__ float g_q   [BATCH*NPIX*CH];      // channel-last
__device__ float g_k   [BATCH*NPIX*CH];      // channel-last
__device__ float g_flow[BATCH*2*NPIX];
__device__ float g_fi  [BATCH*2*NPIX];
__device__ float g_hcat[BATCH*258*NPIX];
__device__ float g_h2  [BATCH*64*NPIX];

// ---------------- helpers ----------------
__device__ __forceinline__ float gelu_f(float v) {
    return 0.5f * v * (1.0f + erff(v * 0.70710678118654752f));
}
__device__ __forceinline__ float sigmoid_f(float v) {
    return 1.0f / (1.0f + expf(-v));
}

#define ACT_NONE 0
#define ACT_GELU 1
#define ACT_SIGM 2

// ---------------- generic NCHW 3x3 conv, pad=1 ----------------
// block: 256 threads (16x16); 2x2 pixels/thread (32x32 tile); COT output
// channels per block; cin staged 8 at a time through smem.
template<int COT>
__global__ __launch_bounds__(256, 2) void conv3x3_kernel(
    const float* __restrict__ in, const float* __restrict__ wgt,
    const float* __restrict__ bias, float* __restrict__ out,
    int Cin, int Cout, int act)
{
    __shared__ float s_in[8][34][34];
    __shared__ float s_w[8][COT][9];

    const int tid = threadIdx.x;
    const int tx = tid & 15, ty = tid >> 4;
    const int x0 = blockIdx.x * 32, y0 = blockIdx.y * 32;
    const int nco = (Cout + COT - 1) / COT;
    const int bb  = blockIdx.z / nco;
    const int co0 = (blockIdx.z % nco) * COT;

    float acc[COT][2][2];
    #pragma unroll
    for (int c = 0; c < COT; c++)
        #pragma unroll
        for (int i = 0; i < 2; i++)
            #pragma unroll
            for (int j = 0; j < 2; j++) acc[c][i][j] = 0.f;

    for (int c0 = 0; c0 < Cin; c0 += 8) {
        // stage 8 input channel tiles (34x34 with halo, zero pad)
        for (int idx = tid; idx < 8 * 1156; idx += 256) {
            int ci = idx / 1156;
            int r  = (idx % 1156) / 34;
            int cc = idx % 34;
            int gy = y0 - 1 + r, gx = x0 - 1 + cc;
            int cin = c0 + ci;
            float v = 0.f;
            if (cin < Cin && (unsigned)gy < (unsigned)HW && (unsigned)gx < (unsigned)HW)
                v = in[((size_t)(bb * Cin + cin) * HW + gy) * HW + gx];
            s_in[ci][r][cc] = v;
        }
        // stage 8 x COT x 9 weights (grid-stride)
        for (int idx = tid; idx < 8 * COT * 9; idx += 256) {
            int ci = idx / (COT * 9);
            int co = (idx % (COT * 9)) / 9;
            int k  = idx % 9;
            int cin = c0 + ci, cog = co0 + co;
            float v = 0.f;
            if (cin < Cin && cog < Cout)
                v = wgt[((size_t)cog * Cin + cin) * 9 + k];
            s_w[ci][co][k] = v;
        }
        __syncthreads();

        #pragma unroll
        for (int ci = 0; ci < 8; ci++) {
            float v[4][4];
            #pragma unroll
            for (int i = 0; i < 4; i++)
                #pragma unroll
                for (int j = 0; j < 4; j++)
                    v[i][j] = s_in[ci][ty * 2 + i][tx * 2 + j];
            #pragma unroll
            for (int co = 0; co < COT; co++) {
                float w0 = s_w[ci][co][0], w1 = s_w[ci][co][1], w2 = s_w[ci][co][2];
                float w3 = s_w[ci][co][3], w4 = s_w[ci][co][4], w5 = s_w[ci][co][5];
                float w6 = s_w[ci][co][6], w7 = s_w[ci][co][7], w8 = s_w[ci][co][8];
                #pragma unroll
                for (int i2 = 0; i2 < 2; i2++)
                    #pragma unroll
                    for (int j2 = 0; j2 < 2; j2++) {
                        float a = acc[co][i2][j2];
                        a += v[i2+0][j2+0] * w0;
                        a += v[i2+0][j2+1] * w1;
                        a += v[i2+0][j2+2] * w2;
                        a += v[i2+1][j2+0] * w3;
                        a += v[i2+1][j2+1] * w4;
                        a += v[i2+1][j2+2] * w5;
                        a += v[i2+2][j2+0] * w6;
                        a += v[i2+2][j2+1] * w7;
                        a += v[i2+2][j2+2] * w8;
                        acc[co][i2][j2] = a;
                    }
            }
        }
        __syncthreads();
    }

    #pragma unroll
    for (int co = 0; co < COT; co++) {
        int cog = co0 + co;
        if (cog >= Cout) break;
        float bv = bias[cog];
        #pragma unroll
        for (int i2 = 0; i2 < 2; i2++)
            #pragma unroll
            for (int j2 = 0; j2 < 2; j2++) {
                int oy = y0 + ty * 2 + i2, ox = x0 + tx * 2 + j2;
                float v = acc[co][i2][j2] + bv;
                if (act == ACT_GELU) v = gelu_f(v);
                else if (act == ACT_SIGM) v = sigmoid_f(v);
                out[((size_t)(bb * Cout + cog) * HW + oy) * HW + ox] = v;
            }
    }
}

// ---------------- fused flow-refiner chain: conv(2->16)+gelu, conv(16->16)+gelu,
// conv(16->2), flow += d. 16x16 output tile with halo recompute, dynamic smem. ----------------
#define FR_OFF_W1 0
#define FR_OFF_B1 288
#define FR_OFF_W2 304
#define FR_OFF_B2 2608
#define FR_OFF_W3 2624
#define FR_OFF_B3 2912
#define FR_OFF_FI 2916            // 2 x 22 x 22 = 968
#define FR_OFF_T1 3884            // 16 x 20 x 20 = 6400
#define FR_OFF_T2 10284           // 16 x 18 x 18 = 5184
#define FR_SMEM_FLOATS 15468
#define FR_SMEM_BYTES (FR_SMEM_FLOATS * 4)

__global__ __launch_bounds__(256) void fr_fused_kernel(
    const float* __restrict__ fi,
    const float* __restrict__ w1, const float* __restrict__ b1,
    const float* __restrict__ w2, const float* __restrict__ b2,
    const float* __restrict__ w3, const float* __restrict__ b3,
    float* __restrict__ flow)
{
    extern __shared__ float sm[];
    const int tid = threadIdx.x;
    const int x0 = blockIdx.x * 16, y0 = blockIdx.y * 16;
    const int b = blockIdx.z;

    // stage weights/biases
    for (int u = tid; u < 288;  u += 256) sm[FR_OFF_W1 + u] = w1[u];
    for (int u = tid; u < 16;   u += 256) sm[FR_OFF_B1 + u] = b1[u];
    for (int u = tid; u < 2304; u += 256) sm[FR_OFF_W2 + u] = w2[u];
    for (int u = tid; u < 16;   u += 256) sm[FR_OFF_B2 + u] = b2[u];
    for (int u = tid; u < 288;  u += 256) sm[FR_OFF_W3 + u] = w3[u];
    for (int u = tid; u < 2;    u += 256) sm[FR_OFF_B3 + u] = b3[u];
    // stage fi region 2 x 22 x 22 (origin y0-3, x0-3), zero pad
    for (int u = tid; u < 2 * 484; u += 256) {
        int ci = u / 484;
        int rem = u % 484;
        int r = rem / 22, c = rem % 22;
        int gy = y0 - 3 + r, gx = x0 - 3 + c;
        float v = 0.f;
        if ((unsigned)gy < (unsigned)HW && (unsigned)gx < (unsigned)HW)
            v = fi[(size_t)(b * 2 + ci) * NPIX + gy * HW + gx];
        sm[FR_OFF_FI + u] = v;
    }
    __syncthreads();

    // conv1: t1[16][20][20], t1 origin (y0-2, x0-2); zero outside image
    for (int u = tid; u < 16 * 400; u += 256) {
        int co = u / 400;
        int rem = u % 400;
        int r = rem / 20, c = rem % 20;
        int gy = y0 - 2 + r, gx = x0 - 2 + c;
        float v = 0.f;
        if ((unsigned)gy < (unsigned)HW && (unsigned)gx < (unsigned)HW) {
            float s = sm[FR_OFF_B1 + co];
            #pragma unroll
            for (int ci = 0; ci < 2; ci++)
                #pragma unroll
                for (int dy = 0; dy < 3; dy++)
                    #pragma unroll
                    for (int dx = 0; dx < 3; dx++)
                        s += sm[FR_OFF_FI + (ci * 22 + r + dy) * 22 + c + dx]
                           * sm[FR_OFF_W1 + (co * 2 + ci) * 9 + dy * 3 + dx];
            v = gelu_f(s);
        }
        sm[FR_OFF_T1 + u] = v;
    }
    __syncthreads();

    // conv2: t2[16][18][18], origin (y0-1, x0-1); zero outside image
    for (int u = tid; u < 16 * 324; u += 256) {
        int co = u / 324;
        int rem = u % 324;
        int r = rem / 18, c = rem % 18;
        int gy = y0 - 1 + r, gx = x0 - 1 + c;
        float v = 0.f;
        if ((unsigned)gy < (unsigned)HW && (unsigned)gx < (unsigned)HW) {
            float s = sm[FR_OFF_B2 + co];
            #pragma unroll
            for (int ci = 0; ci < 16; ci++) {
                const float* t1p = &sm[FR_OFF_T1 + (ci * 20 + r) * 20 + c];
                const float* wp  = &sm[FR_OFF_W2 + (co * 16 + ci) * 9];
                s += t1p[0]  * wp[0] + t1p[1]  * wp[1] + t1p[2]  * wp[2];
                s += t1p[20] * wp[3] + t1p[21] * wp[4] + t1p[22] * wp[5];
                s += t1p[40] * wp[6] + t1p[41] * wp[7] + t1p[42] * wp[8];
            }
            v = gelu_f(s);
        }
        sm[FR_OFF_T2 + u] = v;
    }
    __syncthreads();

    // conv3: d[2][16][16] at (y0, x0); flow += d
    for (int u = tid; u < 2 * 256; u += 256) {
        int f = u / 256;
        int rem = u % 256;
        int r = rem / 16, c = rem % 16;
        float s = sm[FR_OFF_B3 + f];
        #pragma unroll
        for (int ci = 0; ci < 16; ci++) {
            const float* t2p = &sm[FR_OFF_T2 + (ci * 18 + r) * 18 + c];
            const float* wp  = &sm[FR_OFF_W3 + (f * 16 + ci) * 9];
            s += t2p[0]  * wp[0] + t2p[1]  * wp[1] + t2p[2]  * wp[2];
            s += t2p[18] * wp[3] + t2p[19] * wp[4] + t2p[20] * wp[5];
            s += t2p[36] * wp[6] + t2p[37] * wp[7] + t2p[38] * wp[8];
        }
        int gy = y0 + r, gx = x0 + c;
        flow[(size_t)(b * 2 + f) * NPIX + gy * HW + gx] += s;
    }
}

// ---------------- warp + diff + L2-normalize; emits x = 1 - diffn channel-last ----------------
__global__ __launch_bounds__(128) void warp_diff_kernel(
    const float* __restrict__ lf0, const float* __restrict__ lf1,
    const float* __restrict__ flow, float* __restrict__ xout)
{
    __shared__ float s_diff[64][129];
    __shared__ float s_ssq[128];
    __shared__ float s_rinv[64];

    const int tid = threadIdx.x;
    const int b = blockIdx.y;
    const int y = blockIdx.x >> 1;
    const int xbase = (blockIdx.x & 1) * 64;
    const int px = tid & 63;
    const int half = tid >> 6;
    const int x = xbase + px;

    float fx = flow[(b * 2 + 0) * NPIX + y * HW + x];
    float fy = flow[(b * 2 + 1) * NPIX + y * HW + x];
    float xs = fminf(fmaxf((float)x + fx, 0.f), 127.f);
    float ys = fminf(fmaxf((float)y + fy, 0.f), 127.f);
    float x0f = floorf(xs), y0f = floorf(ys);
    int ix0 = (int)x0f, iy0 = (int)y0f;
    int ix1 = min(ix0 + 1, 127), iy1 = min(iy0 + 1, 127);
    float wx = xs - x0f, wy = ys - y0f;
    float w00 = (1.f - wx) * (1.f - wy), w01 = wx * (1.f - wy);
    float w10 = (1.f - wx) * wy,         w11 = wx * wy;
    int o00 = iy0 * HW + ix0, o01 = iy0 * HW + ix1;
    int o10 = iy1 * HW + ix0, o11 = iy1 * HW + ix1;

    const float* lf1b = lf1 + (size_t)b * CH * NPIX;
    const float* lf0b = lf0 + (size_t)b * CH * NPIX;
    const int here = y * HW + x;

    float ssq = 0.f;
    for (int c = half * 64; c < half * 64 + 64; ++c) {
        const float* p = lf1b + (size_t)c * NPIX;
        float wv = w00 * p[o00] + w01 * p[o01] + w10 * p[o10] + w11 * p[o11];
        float d = lf0b[(size_t)c * NPIX + here] - wv;
        s_diff[px][c] = d;
        ssq += d * d;
    }
    s_ssq[tid] = ssq;
    __syncthreads();
    if (tid < 64) {
        float s = s_ssq[tid] + s_ssq[tid + 64];
        s_rinv[tid] = 1.f / fmaxf(sqrtf(s), 1e-12f);
    }
    __syncthreads();

    float* xb = xout + ((size_t)b * NPIX + y * HW + xbase) * CH;
    for (int p2 = 0; p2 < 64; ++p2)
        xb[(size_t)p2 * CH + tid] = 1.f - s_diff[p2][tid] * s_rinv[p2];
}

// ---------------- fused q/k 1x1 projection: [32768,128] x [128,128]^T ----------------
__global__ __launch_bounds__(256) void gemm_qk_kernel(
    const float* __restrict__ X,
    const float* __restrict__ qw, const float* __restrict__ qb,
    const float* __restrict__ kw, const float* __restrict__ kb,
    float* __restrict__ Q, float* __restrict__ Kout)
{
    __shared__ float As[8][132];
    __shared__ float Bs[8][132];

    const int tid = threadIdx.x;
    const int tx = tid & 15, ty = tid >> 4;
    const int m0 = blockIdx.x * 128;
    const bool isK = (blockIdx.y != 0);
    const float* W    = isK ? kw : qw;
    const float* bias = isK ? kb : qb;
    float* out        = isK ? Kout : Q;

    float acc[8][8];
    #pragma unroll
    for (int i = 0; i < 8; i++)
        #pragma unroll
        for (int j = 0; j < 8; j++) acc[i][j] = 0.f;

    const int row  = tid >> 1;   // 0..127
    const int part = tid & 1;

    for (int kk = 0; kk < 128; kk += 8) {
        float4 a = *(const float4*)&X[(size_t)(m0 + row) * 128 + kk + part * 4];
        float4 b = *(const float4*)&W[(size_t)row * 128 + kk + part * 4];
        As[part*4+0][row] = a.x; As[part*4+1][row] = a.y;
        As[part*4+2][row] = a.z; As[part*4+3][row] = a.w;
        Bs[part*4+0][row] = b.x; Bs[part*4+1][row] = b.y;
        Bs[part*4+2][row] = b.z; Bs[part*4+3][row] = b.w;
        __syncthreads();
        #pragma unroll
        for (int k = 0; k < 8; k++) {
            float af[8], bf[8];
            *(float4*)&af[0] = *(const float4*)&As[k][ty * 8];
            *(float4*)&af[4] = *(const float4*)&As[k][ty * 8 + 4];
            *(float4*)&bf[0] = *(const float4*)&Bs[k][tx * 8];
            *(float4*)&bf[4] = *(const float4*)&Bs[k][tx * 8 + 4];
            #pragma unroll
            for (int i = 0; i < 8; i++)
                #pragma unroll
                for (int j = 0; j < 8; j++)
                    acc[i][j] += af[i] * bf[j];
        }
        __syncthreads();
    }

    #pragma unroll
    for (int i = 0; i < 8; i++) {
        int m = m0 + ty * 8 + i;
        #pragma unroll
        for (int j = 0; j < 8; j++)
            out[(size_t)m * 128 + tx * 8 + j] = acc[i][j] + bias[tx * 8 + j];
    }
}

// ---------------- 25-tap local attention ----------------
__global__ __launch_bounds__(256) void attn_kernel(
    const float* __restrict__ Q, const float* __restrict__ K,
    const float* __restrict__ flow, float* __restrict__ fi)
{
    const int lane = threadIdx.x & 31;
    const int warp = threadIdx.x >> 5;
    const int p = blockIdx.x * 8 + warp;     // 0..32767
    const int b = p >> 14;
    const int yx = p & 16383;
    const int y = yx >> 7, x = yx & 127;

    const float* qv = Q + (size_t)p * 128;
    const float q0 = qv[lane], q1 = qv[lane + 32], q2 = qv[lane + 64], q3 = qv[lane + 96];

    float s[25];
    #pragma unroll
    for (int t = 0; t < 25; t++) {
        const int dy = t / 5 - 2, dx = t % 5 - 2;
        const int ny = y + dy, nx = x + dx;
        float partial = 0.f;
        if ((unsigned)ny < (unsigned)HW && (unsigned)nx < (unsigned)HW) {
            const float* kv = K + ((size_t)(b << 14) + ny * HW + nx) * 128;
            partial = q0 * kv[lane] + q1 * kv[lane + 32] + q2 * kv[lane + 64] + q3 * kv[lane + 96];
        }
        #pragma unroll
        for (int off = 16; off; off >>= 1)
            partial += __shfl_xor_sync(0xffffffffu, partial, off);
        s[t] = partial * 0.08838834764831845f;   // 1/sqrt(128)
    }

    float mx = s[0];
    #pragma unroll
    for (int t = 1; t < 25; t++) mx = fmaxf(mx, s[t]);
    float sum = 0.f;
    #pragma unroll
    for (int t = 0; t < 25; t++) sum += expf(s[t] - mx);

    float c0 = 0.f, c1 = 0.f;
    if (lane < 25) {
        const int dy = lane / 5 - 2, dx = lane % 5 - 2;
        const int ny = y + dy, nx = x + dx;
        if ((unsigned)ny < (unsigned)HW && (unsigned)nx < (unsigned)HW) {
            const float w = expf(s[lane] - mx) / sum;
            c0 = w * flow[(size_t)(b * 2 + 0) * NPIX + ny * HW + nx];
            c1 = w * flow[(size_t)(b * 2 + 1) * NPIX + ny * HW + nx];
        }
    }
    #pragma unroll
    for (int off = 16; off; off >>= 1) {
        c0 += __shfl_xor_sync(0xffffffffu, c0, off);
        c1 += __shfl_xor_sync(0xffffffffu, c1, off);
    }
    if (lane == 0) {
        fi[(size_t)(b * 2 + 0) * NPIX + y * HW + x] = c0;
        fi[(size_t)(b * 2 + 1) * NPIX + y * HW + x] = c1;
    }
}

// ---------------- small utility kernels ----------------
__global__ void copy_kernel(float* __restrict__ dst, const float* __restrict__ src, int n) {
    int i = blockIdx.x * 256 + threadIdx.x;
    if (i < n) dst[i] = src[i];
}

// pack hcat = [feat0 | warp(feat1, flow) | flow]
__global__ __launch_bounds__(128) void pack_kernel(
    const float* __restrict__ feat0, const float* __restrict__ feat1,
    const float* __restrict__ flow, float* __restrict__ hcat)
{
    const int x = threadIdx.x;
    const int y = blockIdx.x;
    const int b = blockIdx.y;
    const int here = y * HW + x;

    float fx = flow[(b * 2 + 0) * NPIX + here];
    float fy = flow[(b * 2 + 1) * NPIX + here];
    float xs = fminf(fmaxf((float)x + fx, 0.f), 127.f);
    float ys = fminf(fmaxf((float)y + fy, 0.f), 127.f);
    float x0f = floorf(xs), y0f = floorf(ys);
    int ix0 = (int)x0f, iy0 = (int)y0f;
    int ix1 = min(ix0 + 1, 127), iy1 = min(iy0 + 1, 127);
    float wx = xs - x0f, wy = ys - y0f;
    float w00 = (1.f - wx) * (1.f - wy), w01 = wx * (1.f - wy);
    float w10 = (1.f - wx) * wy,         w11 = wx * wy;
    int o00 = iy0 * HW + ix0, o01 = iy0 * HW + ix1;
    int o10 = iy1 * HW + ix0, o11 = iy1 * HW + ix1;

    float* hb = hcat + (size_t)b * 258 * NPIX;
    const float* f0 = feat0 + (size_t)b * CH * NPIX;
    const float* f1 = feat1 + (size_t)b * CH * NPIX;

    for (int c = 0; c < CH; c++) {
        hb[(size_t)c * NPIX + here] = f0[(size_t)c * NPIX + here];
        const float* p = f1 + (size_t)c * NPIX;
        hb[(size_t)(CH + c) * NPIX + here] =
            w00 * p[o00] + w01 * p[o01] + w10 * p[o10] + w11 * p[o11];
    }
    hb[(size_t)256 * NPIX + here] = fx;
    hb[(size_t)257 * NPIX + here] = fy;
}

// ---------------- host orchestration ----------------
static float* sym_addr(const void* symbol) {
    void* p = nullptr;
    cudaGetSymbolAddress(&p, symbol);
    return (float*)p;
}

extern "C" void kernel_launch(void* const* d_in, const int* in_sizes, int n_in,
                              void* d_out, int out_size)
{
    (void)in_sizes; (void)n_in; (void)out_size;
    const float* feat0     = (const float*)d_in[0];
    const float* feat1     = (const float*)d_in[1];
    const float* flow_init = (const float*)d_in[2];
    const float* lc_w1 = (const float*)d_in[3];
    const float* lc_b1 = (const float*)d_in[4];
    const float* lc_w2 = (const float*)d_in[5];
    const float* lc_b2 = (const float*)d_in[6];
    const float* qw    = (const float*)d_in[7];
    const float* qb    = (const float*)d_in[8];
    const float* kw    = (const float*)d_in[9];
    const float* kb    = (const float*)d_in[10];
    const float* fr_w1 = (const float*)d_in[11];
    const float* fr_b1 = (const float*)d_in[12];
    const float* fr_w2 = (const float*)d_in[13];
    const float* fr_b2 = (const float*)d_in[14];
    const float* fr_w3 = (const float*)d_in[15];
    const float* fr_b3 = (const float*)d_in[16];
    const float* cf_w1 = (const float*)d_in[17];
    const float* cf_b1 = (const float*)d_in[18];
    const float* cf_w2 = (const float*)d_in[19];
    const float* cf_b2 = (const float*)d_in[20];
    const float* cf_w3 = (const float*)d_in[21];
    const float* cf_b3 = (const float*)d_in[22];

    float* lf0  = sym_addr(g_lf0);
    float* lf1  = sym_addr(g_lf1);
    float* tmp  = sym_addr(g_tmp);
    float* xbuf = sym_addr(g_x);
    float* qbuf = sym_addr(g_q);
    float* kbuf = sym_addr(g_k);
    float* flow = sym_addr(g_flow);
    float* fi   = sym_addr(g_fi);
    float* hcat = sym_addr(g_hcat);
    float* h2   = sym_addr(g_h2);
    float* out_flow = (float*)d_out;                 // [B,2,H,W]
    float* out_conf = (float*)d_out + BATCH * 2 * NPIX;  // [B,1,H,W]

    cudaFuncSetAttribute(fr_fused_kernel,
                         cudaFuncAttributeMaxDynamicSharedMemorySize, FR_SMEM_BYTES);

    const dim3 cblk(256);
    // local_conv on both features (hoisted out of the loop)
    conv3x3_kernel<16><<<dim3(4,4,BATCH*8), cblk>>>(feat0, lc_w1, lc_b1, tmp, 128, 128, ACT_GELU);
    conv3x3_kernel<16><<<dim3(4,4,BATCH*8), cblk>>>(tmp,   lc_w2, lc_b2, lf0, 128, 128, ACT_NONE);
    conv3x3_kernel<16><<<dim3(4,4,BATCH*8), cblk>>>(feat1, lc_w1, lc_b1, tmp, 128, 128, ACT_GELU);
    conv3x3_kernel<16><<<dim3(4,4,BATCH*8), cblk>>>(tmp,   lc_w2, lc_b2, lf1, 128, 128, ACT_NONE);

    copy_kernel<<<(BATCH*2*NPIX + 255)/256, 256>>>(flow, flow_init, BATCH*2*NPIX);

    for (int it = 0; it < ITERS; ++it) {
        warp_diff_kernel<<<dim3(2*HW, BATCH), 128>>>(lf0, lf1, flow, xbuf);
        gemm_qk_kernel<<<dim3(BATCH*NPIX/128, 2), 256>>>(xbuf, qw, qb, kw, kb, qbuf, kbuf);
        attn_kernel<<<BATCH*NPIX/8, 256>>>(qbuf, kbuf, flow, fi);
        fr_fused_kernel<<<dim3(8,8,BATCH), 256, FR_SMEM_BYTES>>>(
            fi, fr_w1, fr_b1, fr_w2, fr_b2, fr_w3, fr_b3, flow);
    }

    // confidence head
    pack_kernel<<<dim3(HW, BATCH), 128>>>(feat0, feat1, flow, hcat);
    conv3x3_kernel<16><<<dim3(4,4,BATCH*8), cblk>>>(hcat, cf_w1, cf_b1, tmp, 258, 128, ACT_GELU);
    conv3x3_kernel<16><<<dim3(4,4,BATCH*4), cblk>>>(tmp,  cf_w2, cf_b2, h2,  128, 64,  ACT_GELU);
    conv3x3_kernel<2><<<dim3(4,4,BATCH*1),  cblk>>>(h2,   cf_w3, cf_b3, out_conf, 64, 1, ACT_SIGM);

    copy_kernel<<<(BATCH*2*NPIX + 255)/256, 256>>>(out_flow, flow, BATCH*2*NPIX);
}